// round 13
// baseline (speedup 1.0000x reference)
#include <cuda_runtime.h>
#include <cuda_fp16.h>
#include <cstdint>

#define NPTS     8192
#define NCODES   16384
#define DIM      64
#define NBLK     256          // blocks of 64 codes
#define MARGIN   1.0f         // key-unit margin (error budget ~0.15)

// output layout (floats)
#define OFF_ZQ     0
#define OFF_LOSS   524288
#define OFF_IDX    524289
#define OFF_NUNIQ  532481
#define OFF_USAGE  532482
#define OFF_TOTAL  548866

__device__ float  g_b[NCODES];
__device__ float  g_an[NPTS];
__device__ __half g_zh[NPTS * DIM];              // permuted fp16 z rows
__device__ __half g_eh[NCODES * DIM];            // permuted fp16 (-16384*e) rows
__device__ float  g_bmin[(size_t)NPTS * NBLK];   // 8 MB blockmins [point][block]
__device__ double g_lp[NPTS / 8];                // per-refine-block loss partials
__device__ int    g_done;
__device__ int    g_uniq;

// ---------------------------------------------------------------------------
// helpers
// ---------------------------------------------------------------------------
__device__ __forceinline__ unsigned smem_u32(const void* p) {
    unsigned a;
    asm("{ .reg .u64 t; cvta.to.shared.u64 t, %1; cvt.u32.u64 %0, t; }"
        : "=r"(a) : "l"(p));
    return a;
}
__device__ __forceinline__ void cp_async16(unsigned dst, const void* src) {
    asm volatile("cp.async.cg.shared.global [%0], [%1], 16;" :: "r"(dst), "l"(src));
}
#define CP_COMMIT() asm volatile("cp.async.commit_group;")
#define CP_WAIT1()  asm volatile("cp.async.wait_group 1;")
#define HBAR(id)    asm volatile("bar.sync %0, 128;" :: "r"(id) : "memory")

__device__ __forceinline__ void mma16816(float& d0, float& d1, float& d2, float& d3,
                                         unsigned a0, unsigned a1, unsigned a2, unsigned a3,
                                         unsigned b0, unsigned b1) {
    asm("mma.sync.aligned.m16n8k16.row.col.f32.f16.f16.f32 "
        "{%0,%1,%2,%3},{%4,%5,%6,%7},{%8,%9},{%0,%1,%2,%3};"
        : "+f"(d0), "+f"(d1), "+f"(d2), "+f"(d3)
        : "r"(a0), "r"(a1), "r"(a2), "r"(a3), "r"(b0), "r"(b1));
}

// fragment permutation: half index h (0..63) -> dim d
__device__ __forceinline__ int perm_d(int h) {
    int t = h >> 4, s = (h >> 2) & 3, j = h & 3;
    return 16 * s + 2 * t + (j < 2 ? j : 6 + j);
}

// ---------------------------------------------------------------------------
// P1: fused prep — e rows (all 128 blocks) + z rows (blocks < 64)
// ---------------------------------------------------------------------------
__global__ void vq_prep(const float* __restrict__ z, const float* __restrict__ emb,
                        float* __restrict__ out) {
    const int tid = threadIdx.x;
    // e part: k = bid*128 + tid
    {
        int k = blockIdx.x * 128 + tid;
        const float4* row = (const float4*)(emb + (size_t)k * DIM);
        float ev[64];
        float s = 0.0f;
#pragma unroll
        for (int q = 0; q < 16; ++q) {
            float4 v = row[q];
            ev[q * 4]     = v.x; ev[q * 4 + 1] = v.y;
            ev[q * 4 + 2] = v.z; ev[q * 4 + 3] = v.w;
            s = fmaf(v.x, v.x, s); s = fmaf(v.y, v.y, s);
            s = fmaf(v.z, v.z, s); s = fmaf(v.w, v.w, s);
        }
        g_b[k] = s;
        __half arr[64];
#pragma unroll
        for (int h = 0; h < 64; ++h)
            arr[h] = __float2half(ev[perm_d(h)] * -16384.0f);
        uint4* dst = (uint4*)(g_eh + (size_t)k * 64);
#pragma unroll
        for (int i = 0; i < 8; ++i) dst[i] = ((uint4*)arr)[i];
        out[OFF_USAGE + k] = 0.0f;
        if (k == 0) { g_done = 0; g_uniq = 0; }
    }
    // z part: blocks 0..63
    if (blockIdx.x < 64) {
        int p = blockIdx.x * 128 + tid;
        int b = p >> 10, pos = p & 1023;
        const float* zc = z + (size_t)b * 65536 + pos;
        float s = 0.0f;
        for (int d = 0; d < DIM; ++d) {
            float v = zc[(size_t)d * 1024];
            s = __fadd_rn(s, __fmul_rn(v, v));
        }
        g_an[p] = s;
        __half arr[64];
#pragma unroll
        for (int h = 0; h < 64; ++h)
            arr[h] = __float2half(zc[(size_t)perm_d(h) * 1024]);
        uint4* dst = (uint4*)(g_zh + (size_t)p * 64);
#pragma unroll
        for (int i = 0; i < 8; ++i) dst[i] = ((uint4*)arr)[i];
    }
}

// ---------------------------------------------------------------------------
// K1: HMMA prune — 128 CTAs x 256 thr (8 warps, 2/SMSP).
//     Warps 0-3: points (w&3)*16, tiles 0..63   (codes 0..8191,   ring 0).
//     Warps 4-7: same points,     tiles 64..127 (codes 8192..16383, ring 1).
//     Per-half named barriers decouple the two rings.
//     Output: g_bmin[point][block] f32 (block = 64 codes), all 256 blocks.
// ---------------------------------------------------------------------------
#define TCO     128                      // codes per tile
#define NTILE   64                       // tiles per half
#define ROWB    144
#define SLOTB   (TCO * ROWB)             // 18432
#define RINGB   (3 * SLOTB)              // 55296
#define SMK1    (2 * RINGB)              // 110592

__device__ __forceinline__ void k1_load_tile(unsigned sb, int tileG, int htid) {
    const char* src = (const char*)g_eh + (size_t)tileG * TCO * 128;
#pragma unroll
    for (int i = 0; i < 8; ++i) {
        int u = htid + i * 128;          // 1024 granules
        int r = u >> 3, gr = u & 7;
        cp_async16(sb + r * ROWB + gr * 16, src + r * 128 + gr * 16);
    }
}

__global__ __launch_bounds__(256, 1)
void vq_hmma() {
    extern __shared__ char smem[];
    const unsigned sbase = smem_u32(smem);
    const int tid  = threadIdx.x;
    const int half = tid >> 7;           // 0/1: ring this thread feeds+consumes
    const int htid = tid & 127;
    const int w    = tid >> 5;
    const int lane = tid & 31;
    const int g    = lane >> 2;
    const int t    = lane & 3;
    const int pb   = blockIdx.x * 64 + (w & 3) * 16;   // warp's 16 points
    const int tb   = half * NTILE;                     // warp's tile stream base

    const unsigned ring = sbase + half * RINGB;

    // prologue: this half's first two tiles
    k1_load_tile(ring + 0 * SLOTB, half * NTILE + 0, htid); CP_COMMIT();
    k1_load_tile(ring + 1 * SLOTB, half * NTILE + 1, htid); CP_COMMIT();

    // A fragments (persist whole kernel)
    const uint4* za = (const uint4*)(g_zh + (size_t)(pb + g) * 64);
    const uint4* zb = (const uint4*)(g_zh + (size_t)(pb + g + 8) * 64);
    const uint4 rg0 = za[2 * t], rg1 = za[2 * t + 1];
    const uint4 rh0 = zb[2 * t], rh1 = zb[2 * t + 1];
    unsigned A[4][4] = {
        { rg0.x, rh0.x, rg0.y, rh0.y },
        { rg0.z, rh0.z, rg0.w, rh0.w },
        { rg1.x, rh1.x, rg1.y, rh1.y },
        { rg1.z, rh1.z, rg1.w, rh1.w } };

    const float INF = __int_as_float(0x7f800000);
    float mlo = INF, mhi = INF;

    for (int tt = 0; tt < NTILE; ++tt) {
        CP_WAIT1();
        HBAR(1 + half);                  // tile tt of MY ring resident
        if (tt + 2 < NTILE) k1_load_tile(ring + ((tt + 2) % 3) * SLOTB,
                                         half * NTILE + tt + 2, htid);
        CP_COMMIT();

        const unsigned bs = ring + (tt % 3) * SLOTB;

#pragma unroll 2
        for (int nq = 0; nq < 4; ++nq) {    // 4 n8-tiles per group (32 codes)
            uint4 B0[4], B1[4];
#pragma unroll
            for (int j = 0; j < 4; ++j) {
                unsigned addr = bs + ((nq * 4 + j) * 8 + g) * ROWB + t * 32;
                asm("ld.shared.v4.u32 {%0,%1,%2,%3}, [%4];"
                    : "=r"(B0[j].x), "=r"(B0[j].y), "=r"(B0[j].z), "=r"(B0[j].w)
                    : "r"(addr));
                asm("ld.shared.v4.u32 {%0,%1,%2,%3}, [%4];"
                    : "=r"(B1[j].x), "=r"(B1[j].y), "=r"(B1[j].z), "=r"(B1[j].w)
                    : "r"(addr + 16));
            }
            float D[4][4];
#pragma unroll
            for (int j = 0; j < 4; ++j)
                D[j][0] = D[j][1] = D[j][2] = D[j][3] = 0.0f;
#pragma unroll
            for (int j = 0; j < 4; ++j) {
                mma16816(D[j][0], D[j][1], D[j][2], D[j][3],
                         A[0][0], A[0][1], A[0][2], A[0][3], B0[j].x, B0[j].y);
                mma16816(D[j][0], D[j][1], D[j][2], D[j][3],
                         A[1][0], A[1][1], A[1][2], A[1][3], B0[j].z, B0[j].w);
                mma16816(D[j][0], D[j][1], D[j][2], D[j][3],
                         A[2][0], A[2][1], A[2][2], A[2][3], B1[j].x, B1[j].y);
                mma16816(D[j][0], D[j][1], D[j][2], D[j][3],
                         A[3][0], A[3][1], A[3][2], A[3][3], B1[j].z, B1[j].w);
            }
#pragma unroll
            for (int j = 0; j < 4; ++j) {
                mlo = fminf(mlo, fminf(D[j][0], D[j][1]));
                mhi = fminf(mhi, fminf(D[j][2], D[j][3]));
            }
            if (nq & 1) {                   // block boundary (64 codes)
                float rl = mlo, rh = mhi;
                rl = fminf(rl, __shfl_xor_sync(0xffffffffu, rl, 1));
                rl = fminf(rl, __shfl_xor_sync(0xffffffffu, rl, 2));
                rh = fminf(rh, __shfl_xor_sync(0xffffffffu, rh, 1));
                rh = fminf(rh, __shfl_xor_sync(0xffffffffu, rh, 2));
                if (t == 0) {
                    const int blk = (tb + tt) * 2 + (nq >> 1);   // 0..255
                    g_bmin[(size_t)(pb + g) * NBLK + blk]     = rl;
                    g_bmin[(size_t)(pb + g + 8) * NBLK + blk] = rh;
                }
                mlo = INF; mhi = INF;
            }
        }
        HBAR(1 + half);                     // my half done reading this slot
    }
}

// ---------------------------------------------------------------------------
// K2: flag + exact fp32 refine + FUSED z_q gather and loss.
//     One warp per point (8/CTA, 1024 CTAs); coalesced blockmin reads.
// ---------------------------------------------------------------------------
__global__ __launch_bounds__(256, 2)
void vq_refine(const float* __restrict__ z, const float* __restrict__ emb,
               float* __restrict__ out) {
    __shared__ float  zs[8][64];
    __shared__ float  eq[8][64];
    __shared__ double lred[8];
    __shared__ double sd[256];
    __shared__ int    lastflag;
    const int tid  = threadIdx.x;
    const int w    = tid >> 5;
    const int lane = tid & 31;
    const int p    = blockIdx.x * 8 + w;
    const int b    = p >> 10, pos = p & 1023;

    // stage z row (exact fp32 values)
    zs[w][lane]      = z[(size_t)b * 65536 + (size_t)lane * 1024 + pos];
    zs[w][lane + 32] = z[(size_t)b * 65536 + (size_t)(lane + 32) * 1024 + pos];
    __syncwarp();

    const float a = g_an[p];

    // per-lane 8 blockmins (coalesced: [point][block]), global min
    float bmv[8];
    float gm = __int_as_float(0x7f800000);
#pragma unroll
    for (int i = 0; i < 8; ++i) {
        bmv[i] = g_bmin[(size_t)p * NBLK + i * 32 + lane];
        gm = fminf(gm, bmv[i]);
    }
#pragma unroll
    for (int off = 16; off > 0; off >>= 1)
        gm = fminf(gm, __shfl_xor_sync(0xffffffffu, gm, off));
    const float thr = gm + MARGIN;

    float bd = __int_as_float(0x7f800000);
    int   bk = 0x7fffffff;

#pragma unroll
    for (int i = 0; i < 8; ++i) {
        unsigned m = __ballot_sync(0xffffffffu, bmv[i] < thr);
        while (m) {
            int bit = __ffs(m) - 1;
            m &= m - 1;
            const int blk = i * 32 + bit;
            const int k0 = blk * 64 + 2 * lane;
            const float4* e0 = (const float4*)(emb + (size_t)k0 * DIM);
            const float4* e1 = (const float4*)(emb + (size_t)(k0 + 1) * DIM);
            float c0 = 0.0f, c1 = 0.0f;
#pragma unroll
            for (int q = 0; q < 16; ++q) {
                float4 zz = *(const float4*)&zs[w][q * 4];
                float4 ea = e0[q];
                float4 eb = e1[q];
                c0 = fmaf(zz.x, ea.x, c0); c1 = fmaf(zz.x, eb.x, c1);
                c0 = fmaf(zz.y, ea.y, c0); c1 = fmaf(zz.y, eb.y, c1);
                c0 = fmaf(zz.z, ea.z, c0); c1 = fmaf(zz.z, eb.z, c1);
                c0 = fmaf(zz.w, ea.w, c0); c1 = fmaf(zz.w, eb.w, c1);
            }
            float d0 = fmaf(-2.0f, c0, __fadd_rn(a, g_b[k0]));
            float d1 = fmaf(-2.0f, c1, __fadd_rn(a, g_b[k0 + 1]));
            if (d0 < bd || (d0 == bd && k0 < bk))     { bd = d0; bk = k0;     }
            if (d1 < bd || (d1 == bd && k0 + 1 < bk)) { bd = d1; bk = k0 + 1; }
        }
    }

    // warp argmin with (dist, k) lexicographic tie-break (butterfly: all
    // lanes converge to the same (bd, bk))
#pragma unroll
    for (int off = 16; off > 0; off >>= 1) {
        float od = __shfl_xor_sync(0xffffffffu, bd, off);
        int   ok = __shfl_xor_sync(0xffffffffu, bk, off);
        if (od < bd || (od == bd && ok < bk)) { bd = od; bk = ok; }
    }
    if (lane == 0) {
        out[OFF_IDX + p] = (float)bk;
        float old = atomicExch(&out[OFF_USAGE + bk], 1.0f);
        if (old == 0.0f) atomicAdd(&g_uniq, 1);
    }

    // fused: winner e row -> smem; per-warp fp64 loss partial
    {
        float e0 = emb[(size_t)bk * DIM + lane];
        float e1 = emb[(size_t)bk * DIM + lane + 32];
        eq[w][lane]      = e0;
        eq[w][lane + 32] = e1;
        float f0 = e0 - zs[w][lane];
        float f1 = e1 - zs[w][lane + 32];
        double lacc = (double)f0 * f0 + (double)f1 * f1;
#pragma unroll
        for (int off = 16; off > 0; off >>= 1)
            lacc += __shfl_xor_sync(0xffffffffu, lacc, off);
        if (lane == 0) lred[w] = lacc;
    }
    __syncthreads();

    // cooperative transposed z_q store: 8 consecutive pos per d -> 32B sectors
    {
        const int posb = (blockIdx.x * 8) & 1023;
        const int bb   = (blockIdx.x * 8) >> 10;
        const int pt = tid & 7, ds = tid >> 3;          // ds 0..31
        out[OFF_ZQ + (size_t)bb * 65536 + (size_t)ds * 1024 + posb + pt] =
            eq[pt][ds];
        out[OFF_ZQ + (size_t)bb * 65536 + (size_t)(ds + 32) * 1024 + posb + pt] =
            eq[pt][ds + 32];
    }

    // block loss partial; last arriving block reduces and writes scalars
    if (tid == 0) {
        double tot = 0.0;
#pragma unroll
        for (int i = 0; i < 8; ++i) tot += lred[i];
        g_lp[blockIdx.x] = tot;
        __threadfence();
        lastflag = (atomicAdd(&g_done, 1) == (NPTS / 8) - 1);
    }
    __syncthreads();
    if (lastflag) {
        double s = 0.0;
#pragma unroll
        for (int i = 0; i < 4; ++i) s += g_lp[tid + i * 256];
        sd[tid] = s;
        __syncthreads();
        for (int st = 128; st > 0; st >>= 1) {
            if (tid < st) sd[tid] += sd[tid + st];
            __syncthreads();
        }
        if (tid == 0) {
            float m = (float)(sd[0] / 524288.0);
            out[OFF_LOSS]  = m + 0.25f * m;
            float total = (float)g_uniq;
            out[OFF_NUNIQ] = total;
            out[OFF_TOTAL] = total / (float)NCODES;
        }
    }
}

// ---------------------------------------------------------------------------
extern "C" void kernel_launch(void* const* d_in, const int* in_sizes, int n_in,
                              void* d_out, int out_size) {
    const float* z;
    const float* emb;
    if (in_sizes[0] == 524288) {
        z = (const float*)d_in[0];
        emb = (const float*)d_in[1];
    } else {
        z = (const float*)d_in[1];
        emb = (const float*)d_in[0];
    }
    float* out = (float*)d_out;

    static int attr_set = 0;
    if (!attr_set) {
        cudaFuncSetAttribute(vq_hmma, cudaFuncAttributeMaxDynamicSharedMemorySize, SMK1);
        attr_set = 1;
    }

    vq_prep<<<NCODES / 128, 128>>>(z, emb, out);
    vq_hmma<<<NPTS / 64, 256, SMK1>>>();
    vq_refine<<<NPTS / 8, 256>>>(z, emb, out);
}

// round 14
// speedup vs baseline: 1.0956x; 1.0956x over previous
#include <cuda_runtime.h>
#include <cuda_fp16.h>
#include <cstdint>

#define NPTS     8192
#define NCODES   16384
#define DIM      64
#define NBLK     256          // blocks of 64 codes
#define MARGIN   1.0f         // key-unit margin (error budget ~0.15)

// output layout (floats)
#define OFF_ZQ     0
#define OFF_LOSS   524288
#define OFF_IDX    524289
#define OFF_NUNIQ  532481
#define OFF_USAGE  532482
#define OFF_TOTAL  548866

__device__ float  g_b[NCODES];
__device__ float  g_an[NPTS];
__device__ __half g_zh[NPTS * DIM];              // permuted fp16 z rows
__device__ __half g_eh[NCODES * DIM];            // permuted fp16 (-16384*e) rows
__device__ float  g_bmin[(size_t)NPTS * NBLK];   // 8 MB blockmins [point][block]
__device__ double g_lp[NPTS / 8];                // per-refine-block loss partials
__device__ int    g_done;
__device__ int    g_uniq;

// ---------------------------------------------------------------------------
// helpers
// ---------------------------------------------------------------------------
__device__ __forceinline__ unsigned smem_u32(const void* p) {
    unsigned a;
    asm("{ .reg .u64 t; cvta.to.shared.u64 t, %1; cvt.u32.u64 %0, t; }"
        : "=r"(a) : "l"(p));
    return a;
}
__device__ __forceinline__ void cp_async16(unsigned dst, const void* src) {
    asm volatile("cp.async.cg.shared.global [%0], [%1], 16;" :: "r"(dst), "l"(src));
}
#define CP_COMMIT() asm volatile("cp.async.commit_group;")
#define CP_WAIT1()  asm volatile("cp.async.wait_group 1;")
#define QBAR(id)    asm volatile("bar.sync %0, 128;" :: "r"(id) : "memory")

__device__ __forceinline__ void mma16816(float& d0, float& d1, float& d2, float& d3,
                                         unsigned a0, unsigned a1, unsigned a2, unsigned a3,
                                         unsigned b0, unsigned b1) {
    asm("mma.sync.aligned.m16n8k16.row.col.f32.f16.f16.f32 "
        "{%0,%1,%2,%3},{%4,%5,%6,%7},{%8,%9},{%0,%1,%2,%3};"
        : "+f"(d0), "+f"(d1), "+f"(d2), "+f"(d3)
        : "r"(a0), "r"(a1), "r"(a2), "r"(a3), "r"(b0), "r"(b1));
}

// fragment permutation: half index h (0..63) -> dim d
__device__ __forceinline__ int perm_d(int h) {
    int t = h >> 4, s = (h >> 2) & 3, j = h & 3;
    return 16 * s + 2 * t + (j < 2 ? j : 6 + j);
}

// ---------------------------------------------------------------------------
// P1: fused prep — e rows (all 128 blocks) + z rows (blocks < 64)
// ---------------------------------------------------------------------------
__global__ void vq_prep(const float* __restrict__ z, const float* __restrict__ emb,
                        float* __restrict__ out) {
    const int tid = threadIdx.x;
    // e part: k = bid*128 + tid
    {
        int k = blockIdx.x * 128 + tid;
        const float4* row = (const float4*)(emb + (size_t)k * DIM);
        float ev[64];
        float s = 0.0f;
#pragma unroll
        for (int q = 0; q < 16; ++q) {
            float4 v = row[q];
            ev[q * 4]     = v.x; ev[q * 4 + 1] = v.y;
            ev[q * 4 + 2] = v.z; ev[q * 4 + 3] = v.w;
            s = fmaf(v.x, v.x, s); s = fmaf(v.y, v.y, s);
            s = fmaf(v.z, v.z, s); s = fmaf(v.w, v.w, s);
        }
        g_b[k] = s;
        __half arr[64];
#pragma unroll
        for (int h = 0; h < 64; ++h)
            arr[h] = __float2half(ev[perm_d(h)] * -16384.0f);
        uint4* dst = (uint4*)(g_eh + (size_t)k * 64);
#pragma unroll
        for (int i = 0; i < 8; ++i) dst[i] = ((uint4*)arr)[i];
        out[OFF_USAGE + k] = 0.0f;
        if (k == 0) { g_done = 0; g_uniq = 0; }
    }
    // z part: blocks 0..63
    if (blockIdx.x < 64) {
        int p = blockIdx.x * 128 + tid;
        int b = p >> 10, pos = p & 1023;
        const float* zc = z + (size_t)b * 65536 + pos;
        float s = 0.0f;
        for (int d = 0; d < DIM; ++d) {
            float v = zc[(size_t)d * 1024];
            s = __fadd_rn(s, __fmul_rn(v, v));
        }
        g_an[p] = s;
        __half arr[64];
#pragma unroll
        for (int h = 0; h < 64; ++h)
            arr[h] = __float2half(zc[(size_t)perm_d(h) * 1024]);
        uint4* dst = (uint4*)(g_zh + (size_t)p * 64);
#pragma unroll
        for (int i = 0; i < 8; ++i) dst[i] = ((uint4*)arr)[i];
    }
}

// ---------------------------------------------------------------------------
// K1: HMMA prune — 128 CTAs x 512 thr (16 warps, 4/SMSP).
//     Quarter q = w>>2 owns codes [q*4096, (q+1)*4096) = 64 tiles of 64 codes.
//     Ring q (3 slots) fed + consumed by the same 128 threads (warps 4q..4q+3);
//     per-quarter named barriers. Warp's points: (w&3)*16 within the CTA's 64.
//     Output: g_bmin[point][block] f32 (block = 64 codes), all 256 blocks.
// ---------------------------------------------------------------------------
#define TCO     64                       // codes per tile
#define NTILE   64                       // tiles per quarter
#define ROWB    144
#define SLOTB   (TCO * ROWB)             // 9216
#define RINGB   (3 * SLOTB)              // 27648
#define SMK1    (4 * RINGB)              // 110592

__device__ __forceinline__ void k1_load_tile(unsigned sb, int tileG, int ftid) {
    const char* src = (const char*)g_eh + (size_t)tileG * TCO * 128;
#pragma unroll
    for (int i = 0; i < 4; ++i) {
        int u = ftid + i * 128;          // 512 granules of 16B
        int r = u >> 3, gr = u & 7;
        cp_async16(sb + r * ROWB + gr * 16, src + r * 128 + gr * 16);
    }
}

__global__ __launch_bounds__(512, 1)
void vq_hmma() {
    extern __shared__ char smem[];
    const unsigned sbase = smem_u32(smem);
    const int tid  = threadIdx.x;
    const int q    = tid >> 7;           // quarter 0..3 (ring fed+consumed)
    const int ftid = tid & 127;
    const int w    = tid >> 5;
    const int lane = tid & 31;
    const int g    = lane >> 2;
    const int t    = lane & 3;
    const int pb   = blockIdx.x * 64 + (w & 3) * 16;   // warp's 16 points

    const unsigned ring = sbase + q * RINGB;

    // prologue: this quarter's first two tiles
    k1_load_tile(ring + 0 * SLOTB, q * NTILE + 0, ftid); CP_COMMIT();
    k1_load_tile(ring + 1 * SLOTB, q * NTILE + 1, ftid); CP_COMMIT();

    // A fragments (persist whole kernel)
    const uint4* za = (const uint4*)(g_zh + (size_t)(pb + g) * 64);
    const uint4* zb = (const uint4*)(g_zh + (size_t)(pb + g + 8) * 64);
    const uint4 rg0 = za[2 * t], rg1 = za[2 * t + 1];
    const uint4 rh0 = zb[2 * t], rh1 = zb[2 * t + 1];
    unsigned A[4][4] = {
        { rg0.x, rh0.x, rg0.y, rh0.y },
        { rg0.z, rh0.z, rg0.w, rh0.w },
        { rg1.x, rh1.x, rg1.y, rh1.y },
        { rg1.z, rh1.z, rg1.w, rh1.w } };

    const float INF = __int_as_float(0x7f800000);

    for (int tt = 0; tt < NTILE; ++tt) {
        CP_WAIT1();
        QBAR(1 + q);                     // tile tt of MY ring resident
        if (tt + 2 < NTILE) k1_load_tile(ring + ((tt + 2) % 3) * SLOTB,
                                         q * NTILE + tt + 2, ftid);
        CP_COMMIT();

        const unsigned bs = ring + (tt % 3) * SLOTB;
        float mlo = INF, mhi = INF;

#pragma unroll
        for (int nq = 0; nq < 2; ++nq) {    // 2 groups of 32 codes
            uint4 B0[4], B1[4];
#pragma unroll
            for (int j = 0; j < 4; ++j) {
                unsigned addr = bs + ((nq * 4 + j) * 8 + g) * ROWB + t * 32;
                asm("ld.shared.v4.u32 {%0,%1,%2,%3}, [%4];"
                    : "=r"(B0[j].x), "=r"(B0[j].y), "=r"(B0[j].z), "=r"(B0[j].w)
                    : "r"(addr));
                asm("ld.shared.v4.u32 {%0,%1,%2,%3}, [%4];"
                    : "=r"(B1[j].x), "=r"(B1[j].y), "=r"(B1[j].z), "=r"(B1[j].w)
                    : "r"(addr + 16));
            }
            float D[4][4];
#pragma unroll
            for (int j = 0; j < 4; ++j)
                D[j][0] = D[j][1] = D[j][2] = D[j][3] = 0.0f;
#pragma unroll
            for (int j = 0; j < 4; ++j) {
                mma16816(D[j][0], D[j][1], D[j][2], D[j][3],
                         A[0][0], A[0][1], A[0][2], A[0][3], B0[j].x, B0[j].y);
                mma16816(D[j][0], D[j][1], D[j][2], D[j][3],
                         A[1][0], A[1][1], A[1][2], A[1][3], B0[j].z, B0[j].w);
                mma16816(D[j][0], D[j][1], D[j][2], D[j][3],
                         A[2][0], A[2][1], A[2][2], A[2][3], B1[j].x, B1[j].y);
                mma16816(D[j][0], D[j][1], D[j][2], D[j][3],
                         A[3][0], A[3][1], A[3][2], A[3][3], B1[j].z, B1[j].w);
            }
#pragma unroll
            for (int j = 0; j < 4; ++j) {
                mlo = fminf(mlo, fminf(D[j][0], D[j][1]));
                mhi = fminf(mhi, fminf(D[j][2], D[j][3]));
            }
        }
        // block boundary: tile == block of 64 codes
        {
            float rl = mlo, rh = mhi;
            rl = fminf(rl, __shfl_xor_sync(0xffffffffu, rl, 1));
            rl = fminf(rl, __shfl_xor_sync(0xffffffffu, rl, 2));
            rh = fminf(rh, __shfl_xor_sync(0xffffffffu, rh, 1));
            rh = fminf(rh, __shfl_xor_sync(0xffffffffu, rh, 2));
            if (t == 0) {
                const int blk = q * NTILE + tt;          // 0..255
                g_bmin[(size_t)(pb + g) * NBLK + blk]     = rl;
                g_bmin[(size_t)(pb + g + 8) * NBLK + blk] = rh;
            }
        }
        QBAR(1 + q);                        // my quarter done reading this slot
    }
}

// ---------------------------------------------------------------------------
// K2: flag + exact fp32 refine + FUSED z_q gather and loss.
//     One warp per point (8/CTA, 1024 CTAs); coalesced blockmin reads.
// ---------------------------------------------------------------------------
__global__ __launch_bounds__(256, 2)
void vq_refine(const float* __restrict__ z, const float* __restrict__ emb,
               float* __restrict__ out) {
    __shared__ float  zs[8][64];
    __shared__ float  eq[8][64];
    __shared__ double lred[8];
    __shared__ double sd[256];
    __shared__ int    lastflag;
    const int tid  = threadIdx.x;
    const int w    = tid >> 5;
    const int lane = tid & 31;
    const int p    = blockIdx.x * 8 + w;
    const int b    = p >> 10, pos = p & 1023;

    // stage z row (exact fp32 values)
    zs[w][lane]      = z[(size_t)b * 65536 + (size_t)lane * 1024 + pos];
    zs[w][lane + 32] = z[(size_t)b * 65536 + (size_t)(lane + 32) * 1024 + pos];
    __syncwarp();

    const float a = g_an[p];

    // per-lane 8 blockmins (coalesced: [point][block]), global min
    float bmv[8];
    float gm = __int_as_float(0x7f800000);
#pragma unroll
    for (int i = 0; i < 8; ++i) {
        bmv[i] = g_bmin[(size_t)p * NBLK + i * 32 + lane];
        gm = fminf(gm, bmv[i]);
    }
#pragma unroll
    for (int off = 16; off > 0; off >>= 1)
        gm = fminf(gm, __shfl_xor_sync(0xffffffffu, gm, off));
    const float thr = gm + MARGIN;

    float bd = __int_as_float(0x7f800000);
    int   bk = 0x7fffffff;

#pragma unroll
    for (int i = 0; i < 8; ++i) {
        unsigned m = __ballot_sync(0xffffffffu, bmv[i] < thr);
        while (m) {
            int bit = __ffs(m) - 1;
            m &= m - 1;
            const int blk = i * 32 + bit;
            const int k0 = blk * 64 + 2 * lane;
            const float4* e0 = (const float4*)(emb + (size_t)k0 * DIM);
            const float4* e1 = (const float4*)(emb + (size_t)(k0 + 1) * DIM);
            float c0 = 0.0f, c1 = 0.0f;
#pragma unroll
            for (int qq = 0; qq < 16; ++qq) {
                float4 zz = *(const float4*)&zs[w][qq * 4];
                float4 ea = e0[qq];
                float4 eb = e1[qq];
                c0 = fmaf(zz.x, ea.x, c0); c1 = fmaf(zz.x, eb.x, c1);
                c0 = fmaf(zz.y, ea.y, c0); c1 = fmaf(zz.y, eb.y, c1);
                c0 = fmaf(zz.z, ea.z, c0); c1 = fmaf(zz.z, eb.z, c1);
                c0 = fmaf(zz.w, ea.w, c0); c1 = fmaf(zz.w, eb.w, c1);
            }
            float d0 = fmaf(-2.0f, c0, __fadd_rn(a, g_b[k0]));
            float d1 = fmaf(-2.0f, c1, __fadd_rn(a, g_b[k0 + 1]));
            if (d0 < bd || (d0 == bd && k0 < bk))     { bd = d0; bk = k0;     }
            if (d1 < bd || (d1 == bd && k0 + 1 < bk)) { bd = d1; bk = k0 + 1; }
        }
    }

    // warp argmin with (dist, k) lexicographic tie-break (butterfly: all
    // lanes converge to the same (bd, bk))
#pragma unroll
    for (int off = 16; off > 0; off >>= 1) {
        float od = __shfl_xor_sync(0xffffffffu, bd, off);
        int   ok = __shfl_xor_sync(0xffffffffu, bk, off);
        if (od < bd || (od == bd && ok < bk)) { bd = od; bk = ok; }
    }
    if (lane == 0) {
        out[OFF_IDX + p] = (float)bk;
        float old = atomicExch(&out[OFF_USAGE + bk], 1.0f);
        if (old == 0.0f) atomicAdd(&g_uniq, 1);
    }

    // fused: winner e row -> smem; per-warp fp64 loss partial
    {
        float e0 = emb[(size_t)bk * DIM + lane];
        float e1 = emb[(size_t)bk * DIM + lane + 32];
        eq[w][lane]      = e0;
        eq[w][lane + 32] = e1;
        float f0 = e0 - zs[w][lane];
        float f1 = e1 - zs[w][lane + 32];
        double lacc = (double)f0 * f0 + (double)f1 * f1;
#pragma unroll
        for (int off = 16; off > 0; off >>= 1)
            lacc += __shfl_xor_sync(0xffffffffu, lacc, off);
        if (lane == 0) lred[w] = lacc;
    }
    __syncthreads();

    // cooperative transposed z_q store: 8 consecutive pos per d -> 32B sectors
    {
        const int posb = (blockIdx.x * 8) & 1023;
        const int bb   = (blockIdx.x * 8) >> 10;
        const int pt = tid & 7, ds = tid >> 3;          // ds 0..31
        out[OFF_ZQ + (size_t)bb * 65536 + (size_t)ds * 1024 + posb + pt] =
            eq[pt][ds];
        out[OFF_ZQ + (size_t)bb * 65536 + (size_t)(ds + 32) * 1024 + posb + pt] =
            eq[pt][ds + 32];
    }

    // block loss partial; last arriving block reduces and writes scalars
    if (tid == 0) {
        double tot = 0.0;
#pragma unroll
        for (int i = 0; i < 8; ++i) tot += lred[i];
        g_lp[blockIdx.x] = tot;
        __threadfence();
        lastflag = (atomicAdd(&g_done, 1) == (NPTS / 8) - 1);
    }
    __syncthreads();
    if (lastflag) {
        double s = 0.0;
#pragma unroll
        for (int i = 0; i < 4; ++i) s += g_lp[tid + i * 256];
        sd[tid] = s;
        __syncthreads();
        for (int st = 128; st > 0; st >>= 1) {
            if (tid < st) sd[tid] += sd[tid + st];
            __syncthreads();
        }
        if (tid == 0) {
            float m = (float)(sd[0] / 524288.0);
            out[OFF_LOSS]  = m + 0.25f * m;
            float total = (float)g_uniq;
            out[OFF_NUNIQ] = total;
            out[OFF_TOTAL] = total / (float)NCODES;
        }
    }
}

// ---------------------------------------------------------------------------
extern "C" void kernel_launch(void* const* d_in, const int* in_sizes, int n_in,
                              void* d_out, int out_size) {
    const float* z;
    const float* emb;
    if (in_sizes[0] == 524288) {
        z = (const float*)d_in[0];
        emb = (const float*)d_in[1];
    } else {
        z = (const float*)d_in[1];
        emb = (const float*)d_in[0];
    }
    float* out = (float*)d_out;

    static int attr_set = 0;
    if (!attr_set) {
        cudaFuncSetAttribute(vq_hmma, cudaFuncAttributeMaxDynamicSharedMemorySize, SMK1);
        attr_set = 1;
    }

    vq_prep<<<NCODES / 128, 128>>>(z, emb, out);
    vq_hmma<<<NPTS / 64, 512, SMK1>>>();
    vq_refine<<<NPTS / 8, 256>>>(z, emb, out);
}